// round 15
// baseline (speedup 1.0000x reference)
#include <cuda_runtime.h>
#include <cuda_fp16.h>
#include <cstdint>
#include <math.h>

#define BSZ 8192
#define DIM 128
#define TMM 128
#define TNN 256
#define NT0 2048          // z=0 tiles (64 x 32)
#define NTILES 4096
#define GRID 148
// sqrt(log2(e)/T): rows pre-scaled so exp(sim/T) == ex2(dot)
#define PRESCALE 4.5398160190896614f
#define STAGE 98304       // 96KB per stage: A 32KB + B 64KB
#define SMEM_TOTAL (2 * STAGE)

__device__ double g_partial[2][64];
__device__ __half g_h1[BSZ * DIM];
__device__ __half g_h2[BSZ * DIM];

__device__ __forceinline__ uint32_t smem_u32(const void* p) {
    uint32_t a;
    asm("{ .reg .u64 t; cvta.to.shared.u64 t, %1; cvt.u32.u64 %0, t; }" : "=r"(a) : "l"(p));
    return a;
}
__device__ __forceinline__ void ldsm_x4(uint32_t* r, uint32_t addr) {
    asm volatile("ldmatrix.sync.aligned.m8n8.x4.shared.b16 {%0,%1,%2,%3}, [%4];"
                 : "=r"(r[0]), "=r"(r[1]), "=r"(r[2]), "=r"(r[3]) : "r"(addr));
}
// f16 x f16 -> f16 accum: D packed as 2x half2 (c01 in d0, c23 in d1)
__device__ __forceinline__ void mma_16816_f16(uint32_t* d, const uint32_t* a,
                                              uint32_t b0, uint32_t b1) {
    asm volatile(
        "mma.sync.aligned.m16n8k16.row.col.f16.f16.f16.f16 "
        "{%0,%1}, {%2,%3,%4,%5}, {%6,%7}, {%0,%1};"
        : "+r"(d[0]), "+r"(d[1])
        : "r"(a[0]), "r"(a[1]), "r"(a[2]), "r"(a[3]), "r"(b0), "r"(b1));
}
__device__ __forceinline__ float ex2f(float x) {
    float r;
    asm("ex2.approx.f32 %0, %1;" : "=f"(r) : "f"(x));
    return r;
}
#define CP_ASYNC(dst, src) \
    asm volatile("cp.async.cg.shared.global [%0], [%1], 16;" :: "r"(dst), "l"(src) : "memory")
#define CP_COMMIT() asm volatile("cp.async.commit_group;" ::: "memory")
#define CP_WAIT(n)  asm volatile("cp.async.wait_group %0;" :: "n"(n) : "memory")

// Swizzled smem byte offset: 256B rows, 16B chunks, chunk ^= row&7.
__device__ __forceinline__ int soff(int row, int chunk) {
    return row * 256 + ((chunk ^ (row & 7)) << 4);
}

// ---- loss1 tile classification: excluded k-band per row i is [i, 2i] mod B ----
__device__ __forceinline__ bool tile_skip(int r0, int c0) {
    int r1 = r0 + TMM - 1, c1 = c0 + TNN - 1;
    if (r1 < BSZ / 2) return (c0 >= r1) && (c1 <= 2 * r0);
    return (c0 >= r1) || (c1 <= 2 * r0 - BSZ);
}
__device__ __forceinline__ bool tile_full(int r0, int c0) {
    int r1 = r0 + TMM - 1, c1 = c0 + TNN - 1;
    if (r1 < BSZ / 2) return (c1 < r0) || (c0 > 2 * r1);
    return (c0 > 2 * r1 - BSZ) && (c1 < r0);
}
__device__ __forceinline__ int next_tile(int t) {
    t += GRID;
    while (t < NT0 && tile_skip((t >> 5) * TMM, (t & 31) * TNN)) t += GRID;
    return t;
}

// ---- kernel 1: normalize rows in fp32 (x sqrt(log2e/T)), write fp16 ----
__global__ void prep_kernel(const float* __restrict__ e1, const float* __restrict__ e2) {
    int warp = threadIdx.x >> 5, lane = threadIdx.x & 31;
    int row = blockIdx.x * 8 + warp;
    const float* src = blockIdx.y ? e2 : e1;
    __half* dst = blockIdx.y ? g_h2 : g_h1;
    float4 v = ((const float4*)(src + (size_t)row * DIM))[lane];
    float s = v.x * v.x + v.y * v.y + v.z * v.z + v.w * v.w;
    #pragma unroll
    for (int o = 16; o > 0; o >>= 1) s += __shfl_xor_sync(0xffffffffu, s, o);
    float inv = rsqrtf(s) * PRESCALE;
    __half2 p0 = __float22half2_rn(make_float2(v.x * inv, v.y * inv));
    __half2 p1 = __float22half2_rn(make_float2(v.z * inv, v.w * inv));
    ((__half2*)(dst + (size_t)row * DIM))[lane * 2 + 0] = p0;
    ((__half2*)(dst + (size_t)row * DIM))[lane * 2 + 1] = p1;
    if (blockIdx.x == 0 && blockIdx.y == 0 && threadIdx.x < 128)
        ((double*)g_partial)[threadIdx.x] = 0.0;
}

// ---- prefetch one tile (A 128 rows + B 256 rows) via cp.async ----
__device__ __forceinline__ void prefetch_tile(int t, char* buf, int tid) {
    int z = t >= NT0;
    int tt = t & (NT0 - 1);
    const __half* Ap = g_h1 + (size_t)((tt >> 5) * TMM) * DIM;
    const __half* Bp = (z ? g_h2 : g_h1) + (size_t)((tt & 31) * TNN) * DIM;
    #pragma unroll
    for (int s = 0; s < 4; s++) {
        int l = tid + s * 512, r = l >> 4, c = l & 15;
        CP_ASYNC(smem_u32(buf + soff(r, c)), (const void*)(Ap + (size_t)r * DIM + c * 8));
    }
    #pragma unroll
    for (int s = 0; s < 8; s++) {
        int l = tid + s * 512, r = l >> 4, c = l & 15;
        CP_ASYNC(smem_u32(buf + 32768 + soff(r, c)), (const void*)(Bp + (size_t)r * DIM + c * 8));
    }
}

// ---- kernel 2: persistent double-buffered f16-accum mma GEMM + fused epilogue ----
__global__ __launch_bounds__(512, 1) void tile_kernel() {
    extern __shared__ char smem[];
    const int tid = threadIdx.x;
    const int wid = tid >> 5, lane = tid & 31;
    const int wm = (wid & 3) * 32, wn = (wid >> 2) * 64;

    int t = next_tile((int)blockIdx.x - GRID);
    if (t < NTILES) { prefetch_tile(t, smem, tid); }
    CP_COMMIT();

    float l1 = 0.0f, l2 = 0.0f;
    int cur = 0;

    while (t < NTILES) {
        int tn = next_tile(t);
        if (tn < NTILES) {
            prefetch_tile(tn, smem + (cur ^ 1) * STAGE, tid);
            CP_COMMIT();
            CP_WAIT(1);
        } else {
            CP_WAIT(0);
        }
        __syncthreads();

        const uint32_t sA = smem_u32(smem + cur * STAGE);
        const uint32_t sB = sA + 32768;
        const int z  = t >= NT0;
        const int tt = t & (NT0 - 1);
        const int i0 = (tt >> 5) * TMM;
        const int k0 = (tt & 31) * TNN;
        const bool need_mask = (z == 0) && !tile_full(i0, k0);
        const int gID = lane >> 2, tig = lane & 3;

        // Load ALL A fragments up front (2 mi x 8 k-chunks x 4 regs = 64 regs).
        uint32_t a[2][8][4];
        #pragma unroll
        for (int kk = 0; kk < 8; kk++) {
            #pragma unroll
            for (int mi = 0; mi < 2; mi++) {
                int row = wm + mi * 16 + (lane & 15);
                int chunk = kk * 2 + (lane >> 4);
                ldsm_x4(a[mi][kk], sA + soff(row, chunk));
            }
        }

        float local = 0.0f;
        #pragma unroll
        for (int g = 0; g < 4; g++) {        // 4 n-groups of 16 columns
            uint32_t acc[2][2][2];           // f16x2 accumulators
            #pragma unroll
            for (int mi = 0; mi < 2; mi++)
                #pragma unroll
                for (int jn = 0; jn < 2; jn++)
                    acc[mi][jn][0] = acc[mi][jn][1] = 0u;

            #pragma unroll
            for (int kk = 0; kk < 8; kk++) {
                uint32_t b[4];
                int row = wn + g * 16 + ((lane >> 4) << 3) + (lane & 7);
                int chunk = kk * 2 + ((lane >> 3) & 1);
                ldsm_x4(b, sB + soff(row, chunk));
                #pragma unroll
                for (int mi = 0; mi < 2; mi++)
                    #pragma unroll
                    for (int jn = 0; jn < 2; jn++)
                        mma_16816_f16(acc[mi][jn], a[mi][kk], b[jn * 2], b[jn * 2 + 1]);
            }

            // Epilogue for this n-group (hides under next group's HMMA stream).
            #pragma unroll
            for (int mi = 0; mi < 2; mi++)
                #pragma unroll
                for (int jn = 0; jn < 2; jn++) {
                    float2 v0 = __half22float2(*(__half2*)&acc[mi][jn][0]); // row gID
                    float2 v1 = __half22float2(*(__half2*)&acc[mi][jn][1]); // row gID+8
                    if (need_mask) {
                        int gi0 = i0 + wm + mi * 16 + gID;
                        int gk0 = k0 + wn + g * 16 + jn * 8 + 2 * tig;
                        float e;
                        e = ex2f(v0.x);
                        local += ((((gk0    ) - gi0      ) & (BSZ - 1)) > gi0      ? e : 0.0f);
                        e = ex2f(v0.y);
                        local += ((((gk0 + 1) - gi0      ) & (BSZ - 1)) > gi0      ? e : 0.0f);
                        e = ex2f(v1.x);
                        local += ((((gk0    ) - (gi0 + 8)) & (BSZ - 1)) > (gi0 + 8) ? e : 0.0f);
                        e = ex2f(v1.y);
                        local += ((((gk0 + 1) - (gi0 + 8)) & (BSZ - 1)) > (gi0 + 8) ? e : 0.0f);
                    } else {
                        local += ex2f(v0.x);
                        local += ex2f(v0.y);
                        local += ex2f(v1.x);
                        local += ex2f(v1.y);
                    }
                }
        }
        if (z) l2 += local; else l1 += local;

        __syncthreads();   // all reads of buf done before it is overwritten
        cur ^= 1;
        t = tn;
    }

    #pragma unroll
    for (int o = 16; o > 0; o >>= 1) {
        l1 += __shfl_xor_sync(0xffffffffu, l1, o);
        l2 += __shfl_xor_sync(0xffffffffu, l2, o);
    }
    __shared__ float redA[16], redB[16];
    if (lane == 0) { redA[wid] = l1; redB[wid] = l2; }
    __syncthreads();
    if (tid == 0) {
        float s1 = 0.0f, s2 = 0.0f;
        #pragma unroll
        for (int w = 0; w < 16; w++) { s1 += redA[w]; s2 += redB[w]; }
        int slot = blockIdx.x & 63;
        atomicAdd(&g_partial[0][slot], (double)s1);
        atomicAdd(&g_partial[1][slot], (double)s2);
    }
}

__global__ void final_kernel(float* __restrict__ out) {
    double l1 = 0.0, l2 = 0.0;
    #pragma unroll
    for (int i = 0; i < 64; i++) { l1 += g_partial[0][i]; l2 += g_partial[1][i]; }
    out[0] = (float)(-log(l1 / l2));
}

extern "C" void kernel_launch(void* const* d_in, const int* in_sizes, int n_in,
                              void* d_out, int out_size) {
    const float* e1 = (const float*)d_in[0];
    const float* e2 = (const float*)d_in[1];
    float* out = (float*)d_out;

    prep_kernel<<<dim3(BSZ / 8, 2), 256>>>(e1, e2);

    cudaFuncSetAttribute(tile_kernel, cudaFuncAttributeMaxDynamicSharedMemorySize, SMEM_TOTAL);
    tile_kernel<<<GRID, 512, SMEM_TOTAL>>>();

    final_kernel<<<1, 1>>>(out);
}